// round 10
// baseline (speedup 1.0000x reference)
#include <cuda_runtime.h>
#include <cuda_fp16.h>
#include <cstdint>

// ============================================================================
// ScaledDotProductAttention via mma.sync (HMMA) fp16 GEMMs with hi/lo fp32
// emulation, 2-term everywhere: C = A_hi*B_hi + A_lo*B_hi  (fp32 accum).
// A operands: two fp16 planes [hi | lo] along K (128B smem rows, SW128).
// B operands: hi plane only, DENSE 64B smem rows (SW64) -> stage 24KB,
// NS=3 -> 73KB smem -> 3 CTAs/SM (12 warps/SM) for LDSM/HMMA overlap.
// GEMM: BM=BN=128, 4 warps (2x2) of 64x64 tiles, BK=32 real k per stage.
// ============================================================================

// ---------------- PTX helpers ----------------
__device__ __forceinline__ uint32_t smem_u32(const void* p) {
    uint32_t a;
    asm("{ .reg .u64 t; cvta.to.shared.u64 t, %1; cvt.u32.u64 %0, t; }"
        : "=r"(a) : "l"(p));
    return a;
}
__device__ __forceinline__ void cp16(uint32_t dst, const void* src) {
    asm volatile("cp.async.cg.shared.global [%0], [%1], 16;" :: "r"(dst), "l"(src));
}
__device__ __forceinline__ void cp_commit() {
    asm volatile("cp.async.commit_group;" ::: "memory");
}
template <int N>
__device__ __forceinline__ void cp_wait() {
    asm volatile("cp.async.wait_group %0;" :: "n"(N) : "memory");
}
__device__ __forceinline__ void ldsm_x4(uint32_t* r, uint32_t a) {
    asm volatile("ldmatrix.sync.aligned.m8n8.x4.shared.b16 {%0,%1,%2,%3}, [%4];"
                 : "=r"(r[0]), "=r"(r[1]), "=r"(r[2]), "=r"(r[3]) : "r"(a));
}
__device__ __forceinline__ void mma_f16(float* c, const uint32_t* a,
                                        uint32_t b0, uint32_t b1) {
    asm volatile(
        "mma.sync.aligned.m16n8k16.row.col.f32.f16.f16.f32 "
        "{%0,%1,%2,%3}, {%4,%5,%6,%7}, {%8,%9}, {%0,%1,%2,%3};"
        : "+f"(c[0]), "+f"(c[1]), "+f"(c[2]), "+f"(c[3])
        : "r"(a[0]), "r"(a[1]), "r"(a[2]), "r"(a[3]), "r"(b0), "r"(b1));
}
__device__ __forceinline__ uint32_t swz (uint32_t o) { return o ^ ((o >> 3) & 0x70); }
__device__ __forceinline__ uint32_t swz64(uint32_t o) { return o ^ ((o >> 3) & 0x30); }

__device__ __forceinline__ uint32_t pack_hl(float v0, float v1, bool lo) {
    __half h0 = __float2half_rn(v0);
    __half h1 = __float2half_rn(v1);
    __half a = lo ? __float2half_rn(v0 - __half2float(h0)) : h0;
    __half b = lo ? __float2half_rn(v1 - __half2float(h1)) : h1;
    __half2 p = __halves2half2(a, b);
    return *reinterpret_cast<uint32_t*>(&p);
}

// ---------------- scratch (__device__ globals) ----------------
__device__ __half g_X2 [8192L * 2048];
__device__ __half g_W2 [4][1024L * 2048];
__device__ __half g_Q2 [8192L * 2048];
__device__ __half g_K2 [8192L * 2048];    // lo plane unused (B operand)
__device__ float  g_V  [8192L * 1024];
__device__ __half g_Vt2[4][1024L * 4096]; // lo plane unused (B operand)
__device__ float  g_S  [4L * 2048 * 2048];
__device__ __half g_P2 [4][2048L * 4096];
__device__ __half g_AO2[8192L * 2048];

// ---------------- HMMA GEMM ----------------
// A smem: 128 rows x 128B ([32 hi | 32 lo], SW128) = 16KB
// B smem: 128 rows x  64B (hi only, SW64)          =  8KB
#define NS 3
#define TILE_A 16384
#define TILE_Bb 8192
#define STG_B  (TILE_A + TILE_Bb)
#define SMEM_DYN (1024 + NS * STG_B)

// mode: 0 = fp32 out (*alpha); 1 = fp16 [hi|lo] planes (row stride 2*Ntot);
//       2 = fp16 hi plane only (row stride 2*Ntot, lo untouched)
__global__ __launch_bounds__(128, 3)
void gemm_tc(const __half* __restrict__ Ag, const __half* __restrict__ Bg,
             void* __restrict__ Cout, int Ntot, int Kreal, float alpha, int mode,
             long long sA, long long sB, long long sC)
{
    extern __shared__ char dsm[];
    const uint32_t sb = (smem_u32(dsm) + 1023u) & ~1023u;

    const int tid  = threadIdx.x;
    const int wid  = tid >> 5;
    const int lane = tid & 31;
    const int wm   = wid >> 1;      // 0..1: 64-row block
    const int wn   = wid & 1;       // 0..1: 64-col block
    const int K2   = 2 * Kreal;

    const __half* A = Ag + blockIdx.z * sA + (long long)blockIdx.y * 128 * K2;
    const __half* B = Bg + blockIdx.z * sB + (long long)blockIdx.x * 128 * K2;

    const int NC = Kreal >> 5;      // 32 real k per chunk

    auto load_chunk = [&](int c, int stg) {
        const int k0 = c << 5;
        const uint32_t st = sb + stg * STG_B;
        // A: 128 rows x 8 segs (segs 0-3 hi, 4-7 lo), 128B rows SW128
        #pragma unroll
        for (int i = 0; i < 8; i++) {
            int slot = tid + i * 128;
            int row = slot >> 3, seg = slot & 7;
            int gk = (seg < 4) ? (k0 + seg * 8) : (Kreal + k0 + (seg - 4) * 8);
            cp16(st + swz(row * 128 + seg * 16),
                 A + (long long)row * K2 + gk);
        }
        // B: 128 rows x 4 segs (hi only), dense 64B rows SW64
        #pragma unroll
        for (int i = 0; i < 4; i++) {
            int slot = tid + i * 128;
            int row = slot >> 2, seg = slot & 3;
            cp16(st + TILE_A + swz64(row * 64 + seg * 16),
                 B + (long long)row * K2 + k0 + seg * 8);
        }
        cp_commit();
    };

    float acc[4][8][4];
    #pragma unroll
    for (int i = 0; i < 4; i++)
        #pragma unroll
        for (int j = 0; j < 8; j++)
            #pragma unroll
            for (int k = 0; k < 4; k++) acc[i][j][k] = 0.0f;

    #pragma unroll
    for (int s = 0; s < NS - 1; s++) load_chunk(s, s);

    for (int c = 0; c < NC; c++) {
        if (c + NS - 1 < NC) cp_wait<NS - 2>(); else cp_wait<0>();
        __syncthreads();
        if (c + NS - 1 < NC) load_chunk(c + NS - 1, (c + NS - 1) % NS);

        const uint32_t st = sb + (c % NS) * STG_B;
        const uint32_t aT = st, bT = st + TILE_A;

        #pragma unroll
        for (int ks = 0; ks < 2; ks++) {
            const uint32_t coffH = ks * 32 + (lane >> 4) * 16;  // 0..48
            const uint32_t coffL = 64 + coffH;
            uint32_t ah[4][4], al[4][4];
            #pragma unroll
            for (int mf = 0; mf < 4; mf++) {
                const uint32_t rbase = (wm * 64 + mf * 16 + (lane & 15)) * 128;
                ldsm_x4(ah[mf], aT + swz(rbase + coffH));
                ldsm_x4(al[mf], aT + swz(rbase + coffL));
            }
            #pragma unroll
            for (int bq = 0; bq < 4; bq++) {
                uint32_t bh[4];
                const uint32_t rbase = (wn * 64 + bq * 16 + (lane & 15)) * 64;
                ldsm_x4(bh, bT + swz64(rbase + coffH));
                #pragma unroll
                for (int mf = 0; mf < 4; mf++)
                    #pragma unroll
                    for (int h = 0; h < 2; h++) {
                        float* cc = acc[mf][bq * 2 + h];
                        mma_f16(cc, ah[mf], bh[h], bh[h + 2]);
                        mma_f16(cc, al[mf], bh[h], bh[h + 2]);
                    }
            }
        }
    }

    // ---- epilogue ----
    const int rg = lane >> 2, tg = lane & 3;
    const long long rowBase = (long long)blockIdx.y * 128 + wm * 64;
    const long long colBase = (long long)blockIdx.x * 128 + wn * 64;

    #pragma unroll
    for (int mf = 0; mf < 4; mf++) {
        #pragma unroll
        for (int nf = 0; nf < 8; nf++) {
            const long long r0 = rowBase + mf * 16 + rg;
            const long long cc = colBase + nf * 8 + tg * 2;
            const float* v = acc[mf][nf];
            if (mode == 0) {
                float* Cf = (float*)Cout + blockIdx.z * sC;
                *(float2*)(Cf + r0 * Ntot + cc)       = make_float2(v[0] * alpha, v[1] * alpha);
                *(float2*)(Cf + (r0 + 8) * Ntot + cc) = make_float2(v[2] * alpha, v[3] * alpha);
            } else {
                __half* Cb = (__half*)Cout + blockIdx.z * sC;
                #pragma unroll
                for (int half_i = 0; half_i < 2; half_i++) {
                    const long long rr = r0 + half_i * 8;
                    uint32_t* o = (uint32_t*)(Cb + rr * (2LL * Ntot) + cc);
                    o[0] = pack_hl(v[half_i * 2], v[half_i * 2 + 1], false);
                    if (mode == 1)
                        *(uint32_t*)((__half*)o + Ntot) =
                            pack_hl(v[half_i * 2], v[half_i * 2 + 1], true);
                }
            }
        }
    }
}

// ---------------- splits / transpose / softmax ----------------
// fp32 [R,C] -> fp16 [R,2C]: hi at [r,c], lo at [r,C+c]  (A operands)
__global__ void split_mat(const float* __restrict__ in, __half* __restrict__ out,
                          long long n, int C)
{
    long long e = ((long long)blockIdx.x * blockDim.x + threadIdx.x) * 4;
    if (e >= n) return;
    float4 v = *(const float4*)(in + e);
    long long r = e / C;
    int c = (int)(e - r * C);
    __half* o = out + r * (2LL * C) + c;
    float vv[4] = {v.x, v.y, v.z, v.w};
    #pragma unroll
    for (int i = 0; i < 4; i += 2) {
        *(uint32_t*)(o + i)     = pack_hl(vv[i], vv[i + 1], false);
        *(uint32_t*)(o + C + i) = pack_hl(vv[i], vv[i + 1], true);
    }
}

// all 4 weights in one launch, HI ONLY (weights are B operands)
__global__ void split_w4(const float* __restrict__ w0, const float* __restrict__ w1,
                         const float* __restrict__ w2, const float* __restrict__ w3,
                         __half* __restrict__ out)
{
    const int y = blockIdx.y;
    const float* w = (y == 0) ? w0 : (y == 1) ? w1 : (y == 2) ? w2 : w3;
    long long e = ((long long)blockIdx.x * blockDim.x + threadIdx.x) * 4;
    float4 v = *(const float4*)(w + e);
    long long r = e >> 10;                 // C = 1024
    int c = (int)(e & 1023);
    __half* o = out + (long long)y * 1024 * 2048 + r * 2048 + c;
    float vv[4] = {v.x, v.y, v.z, v.w};
    #pragma unroll
    for (int i = 0; i < 4; i += 2)
        *(uint32_t*)(o + i) = pack_hl(vv[i], vv[i + 1], false);
}

// V fp32 [4][2048][1024] -> Vt2 fp16 [4][1024][2048hi|...] (hi only; B operand)
__global__ void vtrans_split(const float* __restrict__ V, __half* __restrict__ out)
{
    __shared__ float t[32][33];
    const int b = blockIdx.z, s0 = blockIdx.y * 32, d0 = blockIdx.x * 32;
    const int tx = threadIdx.x, ty = threadIdx.y;
    const float* Vb = V + (long long)b * 2048 * 1024;
    #pragma unroll
    for (int i = 0; i < 4; i++) {
        int sy = ty + i * 8;
        t[sy][tx] = Vb[(long long)(s0 + sy) * 1024 + d0 + tx];
    }
    __syncthreads();
    __half* ob = out + (long long)b * 1024 * 4096;
    #pragma unroll
    for (int i = 0; i < 4; i++) {
        int dy = ty + i * 8;
        float v = t[tx][dy];
        ob[(long long)(d0 + dy) * 4096 + s0 + tx] = __float2half_rn(v);
    }
}

// softmax over 2048-wide rows of S, fused split to P2 [hi|lo] (stride 4096)
__global__ void softmax_split(const float* __restrict__ Sg, __half* __restrict__ Pg)
{
    const float4* row = (const float4*)(Sg + (long long)blockIdx.x * 2048);
    const int tid = threadIdx.x;
    float4 a = row[tid];
    float4 b = row[tid + 256];
    float v[8] = {a.x, a.y, a.z, a.w, b.x, b.y, b.z, b.w};

    float m = -1e30f;
    #pragma unroll
    for (int i = 0; i < 8; i++) m = fmaxf(m, v[i]);
    #pragma unroll
    for (int o = 16; o; o >>= 1) m = fmaxf(m, __shfl_xor_sync(0xffffffffu, m, o));
    __shared__ float red[8];
    if ((tid & 31) == 0) red[tid >> 5] = m;
    __syncthreads();
    m = red[0];
    #pragma unroll
    for (int i = 1; i < 8; i++) m = fmaxf(m, red[i]);

    float s = 0.0f;
    #pragma unroll
    for (int i = 0; i < 8; i++) { v[i] = expf(v[i] - m); s += v[i]; }
    #pragma unroll
    for (int o = 16; o; o >>= 1) s += __shfl_xor_sync(0xffffffffu, s, o);
    __syncthreads();
    if ((tid & 31) == 0) red[tid >> 5] = s;
    __syncthreads();
    s = 0.0f;
    #pragma unroll
    for (int i = 0; i < 8; i++) s += red[i];
    const float inv = 1.0f / s;

    __half* P = Pg + (long long)blockIdx.x * 4096;
    #pragma unroll
    for (int half_i = 0; half_i < 2; half_i++) {
        int c = tid * 4 + half_i * 1024;
        #pragma unroll
        for (int i = 0; i < 4; i += 2) {
            float p0 = v[half_i * 4 + i] * inv;
            float p1 = v[half_i * 4 + i + 1] * inv;
            *(uint32_t*)(P + c + i)        = pack_hl(p0, p1, false);
            *(uint32_t*)(P + 2048 + c + i) = pack_hl(p0, p1, true);
        }
    }
}

// ---------------- launch ----------------
extern "C" void kernel_launch(void* const* d_in, const int* in_sizes, int n_in,
                              void* d_out, int out_size)
{
    (void)in_sizes; (void)n_in; (void)out_size;
    const float* x  = (const float*)d_in[0];
    const float* wq = (const float*)d_in[1];
    const float* wk = (const float*)d_in[2];
    const float* wv = (const float*)d_in[3];
    const float* wo = (const float*)d_in[4];
    float* out = (float*)d_out;

    __half *X2, *W2, *Q2, *K2, *Vt2, *P2, *AO2;
    float *V, *S;
    cudaGetSymbolAddress((void**)&X2,  g_X2);
    cudaGetSymbolAddress((void**)&W2,  g_W2);
    cudaGetSymbolAddress((void**)&Q2,  g_Q2);
    cudaGetSymbolAddress((void**)&K2,  g_K2);
    cudaGetSymbolAddress((void**)&V,   g_V);
    cudaGetSymbolAddress((void**)&Vt2, g_Vt2);
    cudaGetSymbolAddress((void**)&S,   g_S);
    cudaGetSymbolAddress((void**)&P2,  g_P2);
    cudaGetSymbolAddress((void**)&AO2, g_AO2);

    cudaFuncSetAttribute(gemm_tc, cudaFuncAttributeMaxDynamicSharedMemorySize, SMEM_DYN);

    // 1) input splits
    split_mat<<<8192, 256>>>(x, X2, 8192LL * 1024, 1024);
    split_w4<<<dim3(1024, 4), 256>>>(wq, wk, wv, wo, W2);

    // 2) projections: M=8192, N=1024, K=1024
    dim3 gp(8, 64, 1), thr(128);
    gemm_tc<<<gp, thr, SMEM_DYN>>>(X2, W2 + 0LL * 1024 * 2048, Q2,
                                   1024, 1024, 1.0f, 1, 0, 0, 0);   // Q: hi+lo
    gemm_tc<<<gp, thr, SMEM_DYN>>>(X2, W2 + 1LL * 1024 * 2048, K2,
                                   1024, 1024, 1.0f, 2, 0, 0, 0);   // K: hi only
    gemm_tc<<<gp, thr, SMEM_DYN>>>(X2, W2 + 2LL * 1024 * 2048, V,
                                   1024, 1024, 1.0f, 0, 0, 0, 0);   // V: fp32

    // 3) scores = Q K^T / 32, per batch: M=N=2048, K=1024
    gemm_tc<<<dim3(16, 16, 4), thr, SMEM_DYN>>>(Q2, K2, S, 2048, 1024,
                                                0.03125f, 0,
                                                2048LL * 2048, 2048LL * 2048,
                                                2048LL * 2048);

    // 4) V transpose (hi only) -> Vt2 [4][1024][4096]
    vtrans_split<<<dim3(32, 64, 4), dim3(32, 8)>>>(V, Vt2);

    // 5) softmax + split -> P2
    softmax_split<<<8192, 256>>>(S, P2);

    // 6) AO = P V, per batch: M=2048, N=1024, K=2048
    gemm_tc<<<dim3(8, 16, 4), thr, SMEM_DYN>>>(P2, Vt2, AO2, 1024, 2048,
                                               1.0f, 1,
                                               2048LL * 4096, 1024LL * 4096,
                                               2048LL * 2048);

    // 7) OUT = AO Wo^T: fp32
    gemm_tc<<<gp, thr, SMEM_DYN>>>(AO2, W2 + 3LL * 1024 * 2048, out,
                                   1024, 1024, 1.0f, 0, 0, 0, 0);
}

// round 11
// speedup vs baseline: 1.9927x; 1.9927x over previous
#include <cuda_runtime.h>
#include <cuda_fp16.h>
#include <cstdint>

// ============================================================================
// ScaledDotProductAttention via mma.sync (HMMA) fp16 GEMMs with hi/lo fp32
// emulation, 2-term everywhere: C = A_hi*B_hi + A_lo*B_hi  (fp32 accum).
// A operands: fp16 planes [hi | lo] along K in gmem; B operands: hi only.
// GEMM: BM=BN=128, 4 warps (2x2) of 64x64 tiles, BK=64 real k per stage
// (three dense 16KB tiles: A_hi, A_lo, B_hi; 128B rows, SW128),
// NS=2 double buffer -> 97KB smem -> 2 CTAs/SM. 16 chunks @ K=1024.
// ============================================================================

// ---------------- PTX helpers ----------------
__device__ __forceinline__ uint32_t smem_u32(const void* p) {
    uint32_t a;
    asm("{ .reg .u64 t; cvta.to.shared.u64 t, %1; cvt.u32.u64 %0, t; }"
        : "=r"(a) : "l"(p));
    return a;
}
__device__ __forceinline__ void cp16(uint32_t dst, const void* src) {
    asm volatile("cp.async.cg.shared.global [%0], [%1], 16;" :: "r"(dst), "l"(src));
}
__device__ __forceinline__ void cp_commit() {
    asm volatile("cp.async.commit_group;" ::: "memory");
}
template <int N>
__device__ __forceinline__ void cp_wait() {
    asm volatile("cp.async.wait_group %0;" :: "n"(N) : "memory");
}
__device__ __forceinline__ void ldsm_x4(uint32_t* r, uint32_t a) {
    asm volatile("ldmatrix.sync.aligned.m8n8.x4.shared.b16 {%0,%1,%2,%3}, [%4];"
                 : "=r"(r[0]), "=r"(r[1]), "=r"(r[2]), "=r"(r[3]) : "r"(a));
}
__device__ __forceinline__ void mma_f16(float* c, const uint32_t* a,
                                        uint32_t b0, uint32_t b1) {
    asm volatile(
        "mma.sync.aligned.m16n8k16.row.col.f32.f16.f16.f32 "
        "{%0,%1,%2,%3}, {%4,%5,%6,%7}, {%8,%9}, {%0,%1,%2,%3};"
        : "+f"(c[0]), "+f"(c[1]), "+f"(c[2]), "+f"(c[3])
        : "r"(a[0]), "r"(a[1]), "r"(a[2]), "r"(a[3]), "r"(b0), "r"(b1));
}
__device__ __forceinline__ uint32_t swz(uint32_t o) { return o ^ ((o >> 3) & 0x70); }

__device__ __forceinline__ uint32_t pack_hl(float v0, float v1, bool lo) {
    __half h0 = __float2half_rn(v0);
    __half h1 = __float2half_rn(v1);
    __half a = lo ? __float2half_rn(v0 - __half2float(h0)) : h0;
    __half b = lo ? __float2half_rn(v1 - __half2float(h1)) : h1;
    __half2 p = __halves2half2(a, b);
    return *reinterpret_cast<uint32_t*>(&p);
}

// ---------------- scratch (__device__ globals) ----------------
__device__ __half g_X2 [8192L * 2048];
__device__ __half g_W2 [4][1024L * 2048];
__device__ __half g_Q2 [8192L * 2048];
__device__ __half g_K2 [8192L * 2048];    // lo plane unused (B operand)
__device__ float  g_V  [8192L * 1024];
__device__ __half g_Vt2[4][1024L * 4096]; // lo plane unused (B operand)
__device__ float  g_S  [4L * 2048 * 2048];
__device__ __half g_P2 [4][2048L * 4096];
__device__ __half g_AO2[8192L * 2048];

// ---------------- HMMA GEMM ----------------
// Stage = A_hi(16KB) + A_lo(16KB) + B_hi(16KB) = 48KB, all 128 rows x 128B
// (= 64 fp16 of k per row), SW128. NS=2 -> 97KB -> 2 CTAs/SM.
#define NS 2
#define TILE_B 16384
#define STG_B  (3 * TILE_B)
#define SMEM_DYN (1024 + NS * STG_B)

// mode: 0 = fp32 out (*alpha); 1 = fp16 [hi|lo] planes (row stride 2*Ntot);
//       2 = fp16 hi plane only (row stride 2*Ntot, lo untouched)
__global__ __launch_bounds__(128, 2)
void gemm_tc(const __half* __restrict__ Ag, const __half* __restrict__ Bg,
             void* __restrict__ Cout, int Ntot, int Kreal, float alpha, int mode,
             long long sA, long long sB, long long sC)
{
    extern __shared__ char dsm[];
    const uint32_t sb = (smem_u32(dsm) + 1023u) & ~1023u;

    const int tid  = threadIdx.x;
    const int wid  = tid >> 5;
    const int lane = tid & 31;
    const int wm   = wid >> 1;      // 0..1: 64-row block
    const int wn   = wid & 1;       // 0..1: 64-col block
    const int K2   = 2 * Kreal;

    const __half* A = Ag + blockIdx.z * sA + (long long)blockIdx.y * 128 * K2;
    const __half* B = Bg + blockIdx.z * sB + (long long)blockIdx.x * 128 * K2;

    const int NC = Kreal >> 6;      // 64 real k per chunk

    auto load_chunk = [&](int c, int stg) {
        const int k0 = c << 6;
        const uint32_t st = sb + stg * STG_B;
        #pragma unroll
        for (int i = 0; i < 8; i++) {
            int slot = tid + i * 128;
            int row = slot >> 3, seg = slot & 7;
            const uint32_t so = swz(row * 128 + seg * 16);
            const long long rb = (long long)row * K2 + k0 + seg * 8;
            cp16(st + so,              A + rb);          // A hi
            cp16(st + TILE_B + so,     A + rb + Kreal);  // A lo
            cp16(st + 2 * TILE_B + so, B + rb);          // B hi
        }
        cp_commit();
    };

    float acc[4][8][4];
    #pragma unroll
    for (int i = 0; i < 4; i++)
        #pragma unroll
        for (int j = 0; j < 8; j++)
            #pragma unroll
            for (int k = 0; k < 4; k++) acc[i][j][k] = 0.0f;

    load_chunk(0, 0);

    for (int c = 0; c < NC; c++) {
        cp_wait<0>();
        __syncthreads();
        if (c + 1 < NC) load_chunk(c + 1, (c + 1) & 1);

        const uint32_t st = sb + (c & 1) * STG_B;
        const uint32_t aH = st, aL = st + TILE_B, bT = st + 2 * TILE_B;

        #pragma unroll
        for (int ks = 0; ks < 4; ks++) {
            const uint32_t coff = ks * 32 + (lane >> 4) * 16;   // 0..127
            uint32_t ah[4][4], al[4][4];
            #pragma unroll
            for (int mf = 0; mf < 4; mf++) {
                const uint32_t rbase = (wm * 64 + mf * 16 + (lane & 15)) * 128;
                const uint32_t so = swz(rbase + coff);
                ldsm_x4(ah[mf], aH + so);
                ldsm_x4(al[mf], aL + so);
            }
            #pragma unroll
            for (int bq = 0; bq < 4; bq++) {
                uint32_t bh[4];
                const uint32_t rbase = (wn * 64 + bq * 16 + (lane & 15)) * 128;
                ldsm_x4(bh, bT + swz(rbase + coff));
                #pragma unroll
                for (int mf = 0; mf < 4; mf++)
                    #pragma unroll
                    for (int h = 0; h < 2; h++) {
                        float* cc = acc[mf][bq * 2 + h];
                        mma_f16(cc, ah[mf], bh[h], bh[h + 2]);
                        mma_f16(cc, al[mf], bh[h], bh[h + 2]);
                    }
            }
        }
    }

    // ---- epilogue ----
    const int rg = lane >> 2, tg = lane & 3;
    const long long rowBase = (long long)blockIdx.y * 128 + wm * 64;
    const long long colBase = (long long)blockIdx.x * 128 + wn * 64;

    #pragma unroll
    for (int mf = 0; mf < 4; mf++) {
        #pragma unroll
        for (int nf = 0; nf < 8; nf++) {
            const long long r0 = rowBase + mf * 16 + rg;
            const long long cc = colBase + nf * 8 + tg * 2;
            const float* v = acc[mf][nf];
            if (mode == 0) {
                float* Cf = (float*)Cout + blockIdx.z * sC;
                *(float2*)(Cf + r0 * Ntot + cc)       = make_float2(v[0] * alpha, v[1] * alpha);
                *(float2*)(Cf + (r0 + 8) * Ntot + cc) = make_float2(v[2] * alpha, v[3] * alpha);
            } else {
                __half* Cb = (__half*)Cout + blockIdx.z * sC;
                #pragma unroll
                for (int half_i = 0; half_i < 2; half_i++) {
                    const long long rr = r0 + half_i * 8;
                    uint32_t* o = (uint32_t*)(Cb + rr * (2LL * Ntot) + cc);
                    o[0] = pack_hl(v[half_i * 2], v[half_i * 2 + 1], false);
                    if (mode == 1)
                        *(uint32_t*)((__half*)o + Ntot) =
                            pack_hl(v[half_i * 2], v[half_i * 2 + 1], true);
                }
            }
        }
    }
}

// ---------------- splits / transpose / softmax ----------------
// fp32 [R,C] -> fp16 [R,2C]: hi at [r,c], lo at [r,C+c]  (A operands)
__global__ void split_mat(const float* __restrict__ in, __half* __restrict__ out,
                          long long n, int C)
{
    long long e = ((long long)blockIdx.x * blockDim.x + threadIdx.x) * 4;
    if (e >= n) return;
    float4 v = *(const float4*)(in + e);
    long long r = e / C;
    int c = (int)(e - r * C);
    __half* o = out + r * (2LL * C) + c;
    float vv[4] = {v.x, v.y, v.z, v.w};
    #pragma unroll
    for (int i = 0; i < 4; i += 2) {
        *(uint32_t*)(o + i)     = pack_hl(vv[i], vv[i + 1], false);
        *(uint32_t*)(o + C + i) = pack_hl(vv[i], vv[i + 1], true);
    }
}

// all 4 weights in one launch, HI ONLY (weights are B operands)
__global__ void split_w4(const float* __restrict__ w0, const float* __restrict__ w1,
                         const float* __restrict__ w2, const float* __restrict__ w3,
                         __half* __restrict__ out)
{
    const int y = blockIdx.y;
    const float* w = (y == 0) ? w0 : (y == 1) ? w1 : (y == 2) ? w2 : w3;
    long long e = ((long long)blockIdx.x * blockDim.x + threadIdx.x) * 4;
    float4 v = *(const float4*)(w + e);
    long long r = e >> 10;                 // C = 1024
    int c = (int)(e & 1023);
    __half* o = out + (long long)y * 1024 * 2048 + r * 2048 + c;
    float vv[4] = {v.x, v.y, v.z, v.w};
    #pragma unroll
    for (int i = 0; i < 4; i += 2)
        *(uint32_t*)(o + i) = pack_hl(vv[i], vv[i + 1], false);
}

// V fp32 [4][2048][1024] -> Vt2 fp16 [4][1024][2048hi|...] (hi only; B operand)
__global__ void vtrans_split(const float* __restrict__ V, __half* __restrict__ out)
{
    __shared__ float t[32][33];
    const int b = blockIdx.z, s0 = blockIdx.y * 32, d0 = blockIdx.x * 32;
    const int tx = threadIdx.x, ty = threadIdx.y;
    const float* Vb = V + (long long)b * 2048 * 1024;
    #pragma unroll
    for (int i = 0; i < 4; i++) {
        int sy = ty + i * 8;
        t[sy][tx] = Vb[(long long)(s0 + sy) * 1024 + d0 + tx];
    }
    __syncthreads();
    __half* ob = out + (long long)b * 1024 * 4096;
    #pragma unroll
    for (int i = 0; i < 4; i++) {
        int dy = ty + i * 8;
        float v = t[tx][dy];
        ob[(long long)(d0 + dy) * 4096 + s0 + tx] = __float2half_rn(v);
    }
}

// softmax over 2048-wide rows of S, fused split to P2 [hi|lo] (stride 4096)
__global__ void softmax_split(const float* __restrict__ Sg, __half* __restrict__ Pg)
{
    const float4* row = (const float4*)(Sg + (long long)blockIdx.x * 2048);
    const int tid = threadIdx.x;
    float4 a = row[tid];
    float4 b = row[tid + 256];
    float v[8] = {a.x, a.y, a.z, a.w, b.x, b.y, b.z, b.w};

    float m = -1e30f;
    #pragma unroll
    for (int i = 0; i < 8; i++) m = fmaxf(m, v[i]);
    #pragma unroll
    for (int o = 16; o; o >>= 1) m = fmaxf(m, __shfl_xor_sync(0xffffffffu, m, o));
    __shared__ float red[8];
    if ((tid & 31) == 0) red[tid >> 5] = m;
    __syncthreads();
    m = red[0];
    #pragma unroll
    for (int i = 1; i < 8; i++) m = fmaxf(m, red[i]);

    float s = 0.0f;
    #pragma unroll
    for (int i = 0; i < 8; i++) { v[i] = expf(v[i] - m); s += v[i]; }
    #pragma unroll
    for (int o = 16; o; o >>= 1) s += __shfl_xor_sync(0xffffffffu, s, o);
    __syncthreads();
    if ((tid & 31) == 0) red[tid >> 5] = s;
    __syncthreads();
    s = 0.0f;
    #pragma unroll
    for (int i = 0; i < 8; i++) s += red[i];
    const float inv = 1.0f / s;

    __half* P = Pg + (long long)blockIdx.x * 4096;
    #pragma unroll
    for (int half_i = 0; half_i < 2; half_i++) {
        int c = tid * 4 + half_i * 1024;
        #pragma unroll
        for (int i = 0; i < 4; i += 2) {
            float p0 = v[half_i * 4 + i] * inv;
            float p1 = v[half_i * 4 + i + 1] * inv;
            *(uint32_t*)(P + c + i)        = pack_hl(p0, p1, false);
            *(uint32_t*)(P + 2048 + c + i) = pack_hl(p0, p1, true);
        }
    }
}

// ---------------- launch ----------------
extern "C" void kernel_launch(void* const* d_in, const int* in_sizes, int n_in,
                              void* d_out, int out_size)
{
    (void)in_sizes; (void)n_in; (void)out_size;
    const float* x  = (const float*)d_in[0];
    const float* wq = (const float*)d_in[1];
    const float* wk = (const float*)d_in[2];
    const float* wv = (const float*)d_in[3];
    const float* wo = (const float*)d_in[4];
    float* out = (float*)d_out;

    __half *X2, *W2, *Q2, *K2, *Vt2, *P2, *AO2;
    float *V, *S;
    cudaGetSymbolAddress((void**)&X2,  g_X2);
    cudaGetSymbolAddress((void**)&W2,  g_W2);
    cudaGetSymbolAddress((void**)&Q2,  g_Q2);
    cudaGetSymbolAddress((void**)&K2,  g_K2);
    cudaGetSymbolAddress((void**)&V,   g_V);
    cudaGetSymbolAddress((void**)&Vt2, g_Vt2);
    cudaGetSymbolAddress((void**)&S,   g_S);
    cudaGetSymbolAddress((void**)&P2,  g_P2);
    cudaGetSymbolAddress((void**)&AO2, g_AO2);

    cudaFuncSetAttribute(gemm_tc, cudaFuncAttributeMaxDynamicSharedMemorySize, SMEM_DYN);

    // 1) input splits
    split_mat<<<8192, 256>>>(x, X2, 8192LL * 1024, 1024);
    split_w4<<<dim3(1024, 4), 256>>>(wq, wk, wv, wo, W2);

    // 2) projections: M=8192, N=1024, K=1024
    dim3 gp(8, 64, 1), thr(128);
    gemm_tc<<<gp, thr, SMEM_DYN>>>(X2, W2 + 0LL * 1024 * 2048, Q2,
                                   1024, 1024, 1.0f, 1, 0, 0, 0);   // Q: hi+lo
    gemm_tc<<<gp, thr, SMEM_DYN>>>(X2, W2 + 1LL * 1024 * 2048, K2,
                                   1024, 1024, 1.0f, 2, 0, 0, 0);   // K: hi only
    gemm_tc<<<gp, thr, SMEM_DYN>>>(X2, W2 + 2LL * 1024 * 2048, V,
                                   1024, 1024, 1.0f, 0, 0, 0, 0);   // V: fp32

    // 3) scores = Q K^T / 32, per batch: M=N=2048, K=1024
    gemm_tc<<<dim3(16, 16, 4), thr, SMEM_DYN>>>(Q2, K2, S, 2048, 1024,
                                                0.03125f, 0,
                                                2048LL * 2048, 2048LL * 2048,
                                                2048LL * 2048);

    // 4) V transpose (hi only) -> Vt2 [4][1024][4096]
    vtrans_split<<<dim3(32, 64, 4), dim3(32, 8)>>>(V, Vt2);

    // 5) softmax + split -> P2
    softmax_split<<<8192, 256>>>(S, P2);

    // 6) AO = P V, per batch: M=2048, N=1024, K=2048
    gemm_tc<<<dim3(8, 16, 4), thr, SMEM_DYN>>>(P2, Vt2, AO2, 1024, 2048,
                                               1.0f, 1,
                                               2048LL * 4096, 1024LL * 4096,
                                               2048LL * 2048);

    // 7) OUT = AO Wo^T: fp32
    gemm_tc<<<gp, thr, SMEM_DYN>>>(AO2, W2 + 3LL * 1024 * 2048, out,
                                   1024, 1024, 1.0f, 0, 0, 0, 0);
}